// round 16
// baseline (speedup 1.0000x reference)
#include <cuda_runtime.h>
#include <math.h>

#define DEC_DIM 1024
#define ENC_DIM 1024
#define BATCH   32
#define SRCLEN  2048

// Per-batch completion counters (zero-init; winner resets after use so every
// graph replay starts clean).
__device__ int g_cnt[BATCH];

__device__ __forceinline__ int atom_add_acq_rel(int* p) {
    int old;
    asm volatile("atom.add.acq_rel.gpu.global.s32 %0, [%1], 1;"
                 : "=r"(old) : "l"(p) : "memory");
    return old;
}

// ---------------------------------------------------------------------------
// Single fused kernel.
// Main body: one warp per (s,b) row (r = s*32+b matches enc memory order,
// consecutive warps stream consecutive 4KB rows; 268MB read once -> HBM-bound).
// Handoff: lane0 plain-stores the raw score then does ONE acq_rel atomicAdd on
// cnt[b]. Release orders the store; NO membar/threadfence anywhere (R10's
// mistake). The warp that sees old==2047 acquires all other stores and runs
// the tanh+softmax epilogue for row b, overlapped with the stream tail.
// ---------------------------------------------------------------------------
__global__ void __launch_bounds__(256)
fused_kernel(const float* __restrict__ enc,        // [SRCLEN][BATCH][ENC_DIM]
             const float* __restrict__ dec_hidden, // [BATCH][DEC_DIM]
             const float* __restrict__ W,          // [1][DEC_DIM+ENC_DIM]
             const float* __restrict__ bias,
             float* __restrict__ out) {            // [BATCH][SRCLEN]
    __shared__ float4 s_w[ENC_DIM / 4];
    const float4* we = reinterpret_cast<const float4*>(W + DEC_DIM);
    for (int i = threadIdx.x; i < ENC_DIM / 4; i += blockDim.x) s_w[i] = we[i];
    __syncthreads();

    const int warp = threadIdx.x >> 5;
    const int lane = threadIdx.x & 31;
    const int r = blockIdx.x * 8 + warp;          // r = s*32 + b, < 65536
    const int b = r & 31;
    const int s = r >> 5;
    const float4* row4 = reinterpret_cast<const float4*>(enc) + (long long)r * (ENC_DIM / 4);

    float sum = 0.f;
#pragma unroll
    for (int i = 0; i < 8; i++) {
        float4 a = __ldcs(row4 + lane + 32 * i);  // streaming: 268MB, zero reuse
        float4 w = s_w[lane + 32 * i];
        sum += a.x * w.x + a.y * w.y + a.z * w.z + a.w * w.w;
    }
#pragma unroll
    for (int o = 16; o; o >>= 1) sum += __shfl_xor_sync(0xffffffffu, sum, o);

    // Handoff: weak payload store + release-flagged counter bump (lane 0 only).
    int old = 0;
    if (lane == 0) {
        out[b * SRCLEN + s] = sum;
        old = atom_add_acq_rel(&g_cnt[b]);
    }
    old = __shfl_sync(0xffffffffu, old, 0);
    if (old != SRCLEN - 1) return;

    // ---- Epilogue: this warp owns completed row b (acquire done above) ----
    // e_dec[b] = dec_hidden[b,:] . W[0,:DEC_DIM] + bias
    float edec;
    {
        const float4* dh = reinterpret_cast<const float4*>(dec_hidden + b * DEC_DIM);
        const float4* wd = reinterpret_cast<const float4*>(W);
        float es = 0.f;
#pragma unroll
        for (int i = 0; i < 8; i++) {
            float4 a = dh[lane + 32 * i];
            float4 w = wd[lane + 32 * i];
            es += a.x * w.x + a.y * w.y + a.z * w.z + a.w * w.w;
        }
#pragma unroll
        for (int o = 16; o; o >>= 1) es += __shfl_xor_sync(0xffffffffu, es, o);
        edec = es + bias[0];
    }

    float4* row = reinterpret_cast<float4*>(out + b * SRCLEN);

    // Pass 1: p = exp(tanh(raw+edec)) (no max pass: tanh bounds exp), store
    // back, accumulate sum. 2048 elems = 512 float4 = 16 per lane, L2-hit.
    float ssum = 0.f;
#pragma unroll
    for (int i = 0; i < 16; i++) {
        float4 v = __ldcg(row + lane + 32 * i);
        v.x = __expf(tanhf(v.x + edec));
        v.y = __expf(tanhf(v.y + edec));
        v.z = __expf(tanhf(v.z + edec));
        v.w = __expf(tanhf(v.w + edec));
        row[lane + 32 * i] = v;
        ssum += v.x + v.y + v.z + v.w;
    }
#pragma unroll
    for (int o = 16; o; o >>= 1) ssum += __shfl_xor_sync(0xffffffffu, ssum, o);
    const float inv = 1.0f / ssum;

    // Pass 2: normalize (L1-hot after pass 1).
#pragma unroll
    for (int i = 0; i < 16; i++) {
        float4 v = row[lane + 32 * i];
        v.x *= inv; v.y *= inv; v.z *= inv; v.w *= inv;
        row[lane + 32 * i] = v;
    }

    if (lane == 0) g_cnt[b] = 0;   // reset for next graph replay
}

// ---------------------------------------------------------------------------
extern "C" void kernel_launch(void* const* d_in, const int* in_sizes, int n_in,
                              void* d_out, int out_size) {
    const float* dec_hidden = (const float*)d_in[0];
    const float* enc        = (const float*)d_in[1];
    const float* W          = (const float*)d_in[2];
    const float* bias       = (const float*)d_in[3];
    float* out = (float*)d_out;

    fused_kernel<<<(SRCLEN * BATCH) / 8, 256>>>(enc, dec_hidden, W, bias, out);
}

// round 17
// speedup vs baseline: 1.3168x; 1.3168x over previous
#include <cuda_runtime.h>
#include <math.h>

#define DEC_DIM 1024
#define ENC_DIM 1024
#define BATCH   32
#define SRCLEN  2048

// Per-batch completion counters, PADDED: one 256-byte line per counter so the
// 65536 release-atomics spread across 32 independent LTS atomic engines
// instead of serializing on one line (the R10/R16 regression).
// Zero-init; the winning warp resets its counter for the next graph replay.
#define CNT_STRIDE 64   // 64 ints = 256 B
__device__ int g_cnt[BATCH * CNT_STRIDE];

__device__ __forceinline__ int atom_add_acq_rel(int* p) {
    int old;
    asm volatile("atom.add.acq_rel.gpu.global.s32 %0, [%1], 1;"
                 : "=r"(old) : "l"(p) : "memory");
    return old;
}

// ---------------------------------------------------------------------------
// Single fused kernel.
// Main body: one warp per (s,b) row (r = s*32+b matches enc memory order,
// consecutive warps stream consecutive 4KB rows; 268MB read once -> HBM-bound).
// Handoff: lane0 plain-stores the raw score then does ONE acq_rel atomicAdd
// on its padded per-b counter (release orders the store; no fences). The warp
// that sees old==2047 acquires all other rows' stores and runs the
// tanh+softmax epilogue for row b, overlapped with the stream tail.
// ---------------------------------------------------------------------------
__global__ void __launch_bounds__(256)
fused_kernel(const float* __restrict__ enc,        // [SRCLEN][BATCH][ENC_DIM]
             const float* __restrict__ dec_hidden, // [BATCH][DEC_DIM]
             const float* __restrict__ W,          // [1][DEC_DIM+ENC_DIM]
             const float* __restrict__ bias,
             float* __restrict__ out) {            // [BATCH][SRCLEN]
    __shared__ float4 s_w[ENC_DIM / 4];
    const float4* we = reinterpret_cast<const float4*>(W + DEC_DIM);
    for (int i = threadIdx.x; i < ENC_DIM / 4; i += blockDim.x) s_w[i] = we[i];
    __syncthreads();

    const int warp = threadIdx.x >> 5;
    const int lane = threadIdx.x & 31;
    const int r = blockIdx.x * 8 + warp;          // r = s*32 + b, < 65536
    const int b = r & 31;
    const int s = r >> 5;
    const float4* row4 = reinterpret_cast<const float4*>(enc) + (long long)r * (ENC_DIM / 4);

    float sum = 0.f;
#pragma unroll
    for (int i = 0; i < 8; i++) {
        float4 a = __ldcs(row4 + lane + 32 * i);  // streaming: 268MB, zero reuse
        float4 w = s_w[lane + 32 * i];
        sum += a.x * w.x + a.y * w.y + a.z * w.z + a.w * w.w;
    }
#pragma unroll
    for (int o = 16; o; o >>= 1) sum += __shfl_xor_sync(0xffffffffu, sum, o);

    // Handoff: weak payload store + release-flagged bump of the PADDED counter.
    int old = 0;
    if (lane == 0) {
        out[b * SRCLEN + s] = sum;
        old = atom_add_acq_rel(&g_cnt[b * CNT_STRIDE]);
    }
    old = __shfl_sync(0xffffffffu, old, 0);
    if (old != SRCLEN - 1) return;

    // ---- Epilogue: this warp owns completed row b (acquire done above) ----
    // e_dec[b] = dec_hidden[b,:] . W[0,:DEC_DIM] + bias
    float edec;
    {
        const float4* dh = reinterpret_cast<const float4*>(dec_hidden + b * DEC_DIM);
        const float4* wd = reinterpret_cast<const float4*>(W);
        float es = 0.f;
#pragma unroll
        for (int i = 0; i < 8; i++) {
            float4 a = dh[lane + 32 * i];
            float4 w = wd[lane + 32 * i];
            es += a.x * w.x + a.y * w.y + a.z * w.z + a.w * w.w;
        }
#pragma unroll
        for (int o = 16; o; o >>= 1) es += __shfl_xor_sync(0xffffffffu, es, o);
        edec = es + bias[0];
    }

    float4* row = reinterpret_cast<float4*>(out + b * SRCLEN);

    // Pass 1: p = exp(tanh(raw+edec)) (no max pass: tanh bounds exp in
    // [1/e, e]), store back, accumulate sum. 512 float4 = 16 per lane, L2-hit.
    float ssum = 0.f;
#pragma unroll
    for (int i = 0; i < 16; i++) {
        float4 v = __ldcg(row + lane + 32 * i);
        v.x = __expf(tanhf(v.x + edec));
        v.y = __expf(tanhf(v.y + edec));
        v.z = __expf(tanhf(v.z + edec));
        v.w = __expf(tanhf(v.w + edec));
        row[lane + 32 * i] = v;
        ssum += v.x + v.y + v.z + v.w;
    }
#pragma unroll
    for (int o = 16; o; o >>= 1) ssum += __shfl_xor_sync(0xffffffffu, ssum, o);
    const float inv = 1.0f / ssum;

    // Pass 2: normalize (L1-hot after pass 1).
#pragma unroll
    for (int i = 0; i < 16; i++) {
        float4 v = row[lane + 32 * i];
        v.x *= inv; v.y *= inv; v.z *= inv; v.w *= inv;
        row[lane + 32 * i] = v;
    }

    if (lane == 0) g_cnt[b * CNT_STRIDE] = 0;   // reset for next graph replay
}

// ---------------------------------------------------------------------------
extern "C" void kernel_launch(void* const* d_in, const int* in_sizes, int n_in,
                              void* d_out, int out_size) {
    const float* dec_hidden = (const float*)d_in[0];
    const float* enc        = (const float*)d_in[1];
    const float* W          = (const float*)d_in[2];
    const float* bias       = (const float*)d_in[3];
    float* out = (float*)d_out;

    fused_kernel<<<(SRCLEN * BATCH) / 8, 256>>>(enc, dec_hidden, W, bias, out);
}